// round 2
// baseline (speedup 1.0000x reference)
#include <cuda_runtime.h>
#include <math.h>

#define NB 2
#define NS 2048
#define ND 1024
#define NH 16
#define NDK 64
#define NTOPK 32

// Scratch for projected Q/K/V, layout [B, S, D] fp32 (head h = cols h*64..h*64+63)
__device__ float g_Qp[NB * NS * ND];
__device__ float g_Kp[NB * NS * ND];
__device__ float g_Vp[NB * NS * ND];

// ---------------------------------------------------------------------------
// Projection GEMM: C[M,N] = relu(A[M,K] @ W[K,N] + bias), M=4096, N=K=1024.
// blockIdx.z in {0,1,2} selects (query,Wq,bq)->Qp, (key,...)->Kp, (value,...)->Vp
// 128x128 block tile, 8x8 per-thread microtile, BK=8, 256 threads.
// ---------------------------------------------------------------------------
__global__ __launch_bounds__(256, 1) void proj_kernel(
    const float* __restrict__ X0, const float* __restrict__ W0, const float* __restrict__ B0,
    const float* __restrict__ X1, const float* __restrict__ W1, const float* __restrict__ B1,
    const float* __restrict__ X2, const float* __restrict__ W2, const float* __restrict__ B2)
{
    const int N = ND, K = ND;
    const int z = blockIdx.z;
    const float* A    = (z == 0) ? X0 : (z == 1) ? X1 : X2;
    const float* W    = (z == 0) ? W0 : (z == 1) ? W1 : W2;
    const float* bias = (z == 0) ? B0 : (z == 1) ? B1 : B2;
    float* C          = (z == 0) ? g_Qp : (z == 1) ? g_Kp : g_Vp;

    __shared__ float As[8][128];   // As[k][m]
    __shared__ float Bs[8][128];   // Bs[k][n]

    const int tid = threadIdx.x;
    const int tx = tid & 15;       // 0..15 -> n microtile
    const int ty = tid >> 4;       // 0..15 -> m microtile
    const int brow = blockIdx.y * 128;
    const int bcol = blockIdx.x * 128;

    // global load mapping
    const int lr = tid >> 1;            // A row within tile (0..127)
    const int lc = (tid & 1) << 2;      // A k-offset (0 or 4)
    const int wr = tid >> 5;            // W row within k-slab (0..7)
    const int wc = (tid & 31) << 2;     // W col (0..124)

    float acc[8][8];
#pragma unroll
    for (int i = 0; i < 8; i++)
#pragma unroll
        for (int j = 0; j < 8; j++) acc[i][j] = 0.0f;

    const float* Aptr = A + (size_t)(brow + lr) * K + lc;
    const float* Wptr = W + (size_t)wr * N + bcol + wc;

    for (int k0 = 0; k0 < K; k0 += 8) {
        float4 a = *(const float4*)(Aptr + k0);
        float4 w = *(const float4*)(Wptr + (size_t)k0 * N);
        __syncthreads();
        As[lc + 0][lr] = a.x;
        As[lc + 1][lr] = a.y;
        As[lc + 2][lr] = a.z;
        As[lc + 3][lr] = a.w;
        *(float4*)&Bs[wr][wc] = w;
        __syncthreads();
#pragma unroll
        for (int k = 0; k < 8; k++) {
            float4 a0 = *(const float4*)&As[k][ty * 8];
            float4 a1 = *(const float4*)&As[k][ty * 8 + 4];
            float4 b0 = *(const float4*)&Bs[k][tx * 8];
            float4 b1 = *(const float4*)&Bs[k][tx * 8 + 4];
            float ar[8] = {a0.x, a0.y, a0.z, a0.w, a1.x, a1.y, a1.z, a1.w};
            float br[8] = {b0.x, b0.y, b0.z, b0.w, b1.x, b1.y, b1.z, b1.w};
#pragma unroll
            for (int i = 0; i < 8; i++)
#pragma unroll
                for (int j = 0; j < 8; j++)
                    acc[i][j] += ar[i] * br[j];
        }
    }

#pragma unroll
    for (int i = 0; i < 8; i++) {
        const int r = brow + ty * 8 + i;
        float* crow = C + (size_t)r * N + bcol + tx * 8;
#pragma unroll
        for (int j = 0; j < 8; j += 4) {
            const int c = bcol + tx * 8 + j;
            float4 v;
            v.x = fmaxf(acc[i][j + 0] + bias[c + 0], 0.0f);
            v.y = fmaxf(acc[i][j + 1] + bias[c + 1], 0.0f);
            v.z = fmaxf(acc[i][j + 2] + bias[c + 2], 0.0f);
            v.w = fmaxf(acc[i][j + 3] + bias[c + 3], 0.0f);
            *(float4*)(crow + j) = v;
        }
    }
}

// ---------------------------------------------------------------------------
// Warp helpers
// ---------------------------------------------------------------------------
__device__ __forceinline__ float warp_max(float v) {
#pragma unroll
    for (int off = 16; off > 0; off >>= 1)
        v = fmaxf(v, __shfl_xor_sync(0xffffffffu, v, off));
    return v;
}

__device__ __forceinline__ float warp_sum(float v) {
#pragma unroll
    for (int off = 16; off > 0; off >>= 1)
        v += __shfl_xor_sync(0xffffffffu, v, off);
    return v;
}

// argmin over one value per lane -> (min value, min lane) broadcast to all lanes.
// Ties resolve to the lowest lane (deterministic).
__device__ __forceinline__ void warp_argmin(float v, int lane, float& mv, int& ml) {
    float m = v;
    int   l = lane;
#pragma unroll
    for (int off = 16; off > 0; off >>= 1) {
        float om = __shfl_xor_sync(0xffffffffu, m, off);
        int   ol = __shfl_xor_sync(0xffffffffu, l, off);
        if (om < m || (om == m && ol < l)) { m = om; l = ol; }
    }
    mv = m;
    ml = l;
}

// Insert 32 candidate scores (one per lane) into a warp-distributed top-32 list.
// Strict '>' keeps earlier (lower-index) entries on ties, matching jax.lax.top_k.
__device__ __forceinline__ void topk_insert(float s, int idx, int lane,
                                            float& lval, int& lidx,
                                            float& curmin, int& minlane)
{
    unsigned bal = __ballot_sync(0xffffffffu, s > curmin);
    while (bal) {
        const int src = __ffs(bal) - 1;
        bal &= bal - 1;
        const float v  = __shfl_sync(0xffffffffu, s, src);
        const int   vi = __shfl_sync(0xffffffffu, idx, src);
        if (v > curmin) {                 // uniform branch (curmin is warp-uniform)
            if (lane == minlane) { lval = v; lidx = vi; }
            warp_argmin(lval, lane, curmin, minlane);
        }
    }
}

// ---------------------------------------------------------------------------
// Attention: one warp handles 2 query rows of one (b,h).
// Streams K in 32-row smem tiles; lane j scores k-row j of the tile against
// both q rows (q rows live in registers). Maintains top-32 online, then
// softmax over the 32 survivors and a 32-row gather from V.
// Block = 256 threads (8 warps -> 16 rows). Grid = (S/16, H, B).
// ---------------------------------------------------------------------------
__global__ __launch_bounds__(256, 1) void attn_kernel(float* __restrict__ out)
{
    const int b    = blockIdx.z;
    const int h    = blockIdx.y;
    const int warp = threadIdx.x >> 5;
    const int lane = threadIdx.x & 31;
    const int r0   = blockIdx.x * 16 + warp * 2;
    const int r1   = r0 + 1;

    __shared__ float4 ksh[32 * 16];   // 32 k-rows x 16 float4, xor-swizzled

    const float4* Qp4 = (const float4*)g_Qp;
    const float4* Kp4 = (const float4*)g_Kp;

    // q rows in registers (uniform across lanes)
    float4 q0[16], q1[16];
    {
        const float4* p0 = Qp4 + (size_t)(b * NS + r0) * (ND / 4) + h * (NDK / 4);
        const float4* p1 = Qp4 + (size_t)(b * NS + r1) * (ND / 4) + h * (NDK / 4);
#pragma unroll
        for (int i = 0; i < 16; i++) { q0[i] = p0[i]; q1[i] = p1[i]; }
    }

    float lval0 = -INFINITY, lval1 = -INFINITY;
    int   lidx0 = 0, lidx1 = 0;
    float curmin0 = -INFINITY, curmin1 = -INFINITY;
    int   minlane0 = 0, minlane1 = 0;

    const int sw = lane & 7;  // swizzle key for this lane's k-row reads

    for (int tile = 0; tile < NS / 32; ++tile) {
        __syncthreads();
        // cooperative load of 32x64 fp32 K tile (512 float4), swizzled
#pragma unroll
        for (int q = 0; q < 2; q++) {
            const int f = threadIdx.x + q * 256;
            const int j = f >> 4;
            const int i = f & 15;
            float4 v = Kp4[(size_t)(b * NS + tile * 32 + j) * (ND / 4) + h * 16 + i];
            ksh[(j << 4) | (i ^ (j & 7))] = v;
        }
        __syncthreads();

        // lane computes score of k-row (tile*32 + lane) against q0 and q1
        float a0x = 0.f, a0y = 0.f, a0z = 0.f, a0w = 0.f;
        float a1x = 0.f, a1y = 0.f, a1z = 0.f, a1w = 0.f;
#pragma unroll
        for (int i = 0; i < 16; i++) {
            const float4 kv = ksh[(lane << 4) | (i ^ sw)];
            a0x += q0[i].x * kv.x; a0y += q0[i].y * kv.y;
            a0z += q0[i].z * kv.z; a0w += q0[i].w * kv.w;
            a1x += q1[i].x * kv.x; a1y += q1[i].y * kv.y;
            a1z += q1[i].z * kv.z; a1w += q1[i].w * kv.w;
        }
        const float s0 = ((a0x + a0y) + (a0z + a0w)) * 0.125f;  // 1/sqrt(64)
        const float s1 = ((a1x + a1y) + (a1z + a1w)) * 0.125f;
        const int idx = tile * 32 + lane;

        topk_insert(s0, idx, lane, lval0, lidx0, curmin0, minlane0);
        topk_insert(s1, idx, lane, lval1, lidx1, curmin1, minlane1);
    }

    // softmax over the 32 survivors (exactly equals reference masked softmax:
    // masked entries contribute exp(-1e9 - max) == 0 in fp32)
    const float m0 = warp_max(lval0);
    const float e0 = __expf(lval0 - m0);
    const float w0 = e0 / warp_sum(e0);

    const float m1 = warp_max(lval1);
    const float e1 = __expf(lval1 - m1);
    const float w1 = e1 / warp_sum(e1);

    // AV gather: lane owns output dims (2*lane, 2*lane+1)
    const float* Vb = g_Vp + (size_t)b * NS * ND + h * NDK + lane * 2;
    float2 acc0 = make_float2(0.f, 0.f);
    float2 acc1 = make_float2(0.f, 0.f);
#pragma unroll
    for (int t = 0; t < 32; t++) {
        const int   vi0 = __shfl_sync(0xffffffffu, lidx0, t);
        const float wt0 = __shfl_sync(0xffffffffu, w0, t);
        const float2 v0 = *(const float2*)(Vb + (size_t)vi0 * ND);
        acc0.x += wt0 * v0.x; acc0.y += wt0 * v0.y;

        const int   vi1 = __shfl_sync(0xffffffffu, lidx1, t);
        const float wt1 = __shfl_sync(0xffffffffu, w1, t);
        const float2 v1 = *(const float2*)(Vb + (size_t)vi1 * ND);
        acc1.x += wt1 * v1.x; acc1.y += wt1 * v1.y;
    }

    *(float2*)(out + (size_t)(b * NS + r0) * ND + h * NDK + lane * 2) = acc0;
    *(float2*)(out + (size_t)(b * NS + r1) * ND + h * NDK + lane * 2) = acc1;
}

// ---------------------------------------------------------------------------
extern "C" void kernel_launch(void* const* d_in, const int* in_sizes, int n_in,
                              void* d_out, int out_size)
{
    const float* query = (const float*)d_in[0];
    const float* key   = (const float*)d_in[1];
    const float* value = (const float*)d_in[2];
    const float* Wq    = (const float*)d_in[3];
    const float* bq    = (const float*)d_in[4];
    const float* Wk    = (const float*)d_in[5];
    const float* bk    = (const float*)d_in[6];
    const float* Wv    = (const float*)d_in[7];
    const float* bv    = (const float*)d_in[8];
    float* out = (float*)d_out;

    dim3 pgrid(ND / 128, (NB * NS) / 128, 3);
    proj_kernel<<<pgrid, 256>>>(query, Wq, bq, key, Wk, bk, value, Wv, bv);

    dim3 agrid(NS / 16, NH, NB);
    attn_kernel<<<agrid, 256>>>(out);
}

// round 3
// speedup vs baseline: 1.6444x; 1.6444x over previous
#include <cuda_runtime.h>
#include <math.h>

#define NB 2
#define NS 2048
#define ND 1024
#define NH 16
#define NDK 64
#define NTOPK 32
#define NTILES (NS / 32)

// Scratch for projected Q/K/V, layout [B, S, D] fp32 (head h = cols h*64..h*64+63)
__device__ float g_Qp[NB * NS * ND];
__device__ float g_Kp[NB * NS * ND];
__device__ float g_Vp[NB * NS * ND];

// ---------------------------------------------------------------------------
// Projection GEMM: C[M,N] = relu(A[M,K] @ W[K,N] + bias), M=4096, N=K=1024.
// ---------------------------------------------------------------------------
__global__ __launch_bounds__(256, 1) void proj_kernel(
    const float* __restrict__ X0, const float* __restrict__ W0, const float* __restrict__ B0,
    const float* __restrict__ X1, const float* __restrict__ W1, const float* __restrict__ B1,
    const float* __restrict__ X2, const float* __restrict__ W2, const float* __restrict__ B2)
{
    const int N = ND, K = ND;
    const int z = blockIdx.z;
    const float* A    = (z == 0) ? X0 : (z == 1) ? X1 : X2;
    const float* W    = (z == 0) ? W0 : (z == 1) ? W1 : W2;
    const float* bias = (z == 0) ? B0 : (z == 1) ? B1 : B2;
    float* C          = (z == 0) ? g_Qp : (z == 1) ? g_Kp : g_Vp;

    __shared__ float As[8][128];
    __shared__ float Bs[8][128];

    const int tid = threadIdx.x;
    const int tx = tid & 15;
    const int ty = tid >> 4;
    const int brow = blockIdx.y * 128;
    const int bcol = blockIdx.x * 128;

    const int lr = tid >> 1;
    const int lc = (tid & 1) << 2;
    const int wr = tid >> 5;
    const int wc = (tid & 31) << 2;

    float acc[8][8];
#pragma unroll
    for (int i = 0; i < 8; i++)
#pragma unroll
        for (int j = 0; j < 8; j++) acc[i][j] = 0.0f;

    const float* Aptr = A + (size_t)(brow + lr) * K + lc;
    const float* Wptr = W + (size_t)wr * N + bcol + wc;

    for (int k0 = 0; k0 < K; k0 += 8) {
        float4 a = *(const float4*)(Aptr + k0);
        float4 w = *(const float4*)(Wptr + (size_t)k0 * N);
        __syncthreads();
        As[lc + 0][lr] = a.x;
        As[lc + 1][lr] = a.y;
        As[lc + 2][lr] = a.z;
        As[lc + 3][lr] = a.w;
        *(float4*)&Bs[wr][wc] = w;
        __syncthreads();
#pragma unroll
        for (int k = 0; k < 8; k++) {
            float4 a0 = *(const float4*)&As[k][ty * 8];
            float4 a1 = *(const float4*)&As[k][ty * 8 + 4];
            float4 b0 = *(const float4*)&Bs[k][tx * 8];
            float4 b1 = *(const float4*)&Bs[k][tx * 8 + 4];
            float ar[8] = {a0.x, a0.y, a0.z, a0.w, a1.x, a1.y, a1.z, a1.w};
            float br[8] = {b0.x, b0.y, b0.z, b0.w, b1.x, b1.y, b1.z, b1.w};
#pragma unroll
            for (int i = 0; i < 8; i++)
#pragma unroll
                for (int j = 0; j < 8; j++)
                    acc[i][j] += ar[i] * br[j];
        }
    }

#pragma unroll
    for (int i = 0; i < 8; i++) {
        const int r = brow + ty * 8 + i;
        float* crow = C + (size_t)r * N + bcol + tx * 8;
#pragma unroll
        for (int j = 0; j < 8; j += 4) {
            const int c = bcol + tx * 8 + j;
            float4 v;
            v.x = fmaxf(acc[i][j + 0] + bias[c + 0], 0.0f);
            v.y = fmaxf(acc[i][j + 1] + bias[c + 1], 0.0f);
            v.z = fmaxf(acc[i][j + 2] + bias[c + 2], 0.0f);
            v.w = fmaxf(acc[i][j + 3] + bias[c + 3], 0.0f);
            *(float4*)(crow + j) = v;
        }
    }
}

// ---------------------------------------------------------------------------
// Helpers
// ---------------------------------------------------------------------------
__device__ __forceinline__ float warp_max(float v) {
#pragma unroll
    for (int off = 16; off > 0; off >>= 1)
        v = fmaxf(v, __shfl_xor_sync(0xffffffffu, v, off));
    return v;
}

__device__ __forceinline__ float warp_sum(float v) {
#pragma unroll
    for (int off = 16; off > 0; off >>= 1)
        v += __shfl_xor_sync(0xffffffffu, v, off);
    return v;
}

// Monotone float->uint transform: u-order == float-order (finite values).
__device__ __forceinline__ unsigned f2mono(float f) {
    unsigned b = __float_as_uint(f);
    return (b & 0x80000000u) ? ~b : (b | 0x80000000u);
}
__device__ __forceinline__ float mono2f(unsigned u) {
    unsigned b = (u & 0x80000000u) ? (u ^ 0x80000000u) : ~u;
    return __uint_as_float(b);
}

// Insert one candidate-per-lane batch into the warp-distributed top-32 list.
// All comparisons in u-space. Strict '>' keeps earliest (lowest index) on
// ties, matching jax.lax.top_k. Min tracked via REDUX (short chain).
__device__ __forceinline__ void insert_u(unsigned us, int idx, int lane,
                                         unsigned& lu, int& lidx,
                                         unsigned& umin, int& minlane)
{
    unsigned bal = __ballot_sync(0xffffffffu, us > umin);
    while (bal) {
        const int src = __ffs(bal) - 1;
        bal &= bal - 1;
        const unsigned uv = __shfl_sync(0xffffffffu, us, src);
        const int      vi = __shfl_sync(0xffffffffu, idx, src);
        if (uv > umin) {               // umin warp-uniform -> uniform branch
            if (lane == minlane) { lu = uv; lidx = vi; }
            umin = __reduce_min_sync(0xffffffffu, lu);
            minlane = __ffs(__ballot_sync(0xffffffffu, lu == umin)) - 1;
        }
    }
}

__device__ __forceinline__ void cp_async16(unsigned saddr, const void* gaddr) {
    asm volatile("cp.async.cg.shared.global [%0], [%1], 16;\n"
                 :: "r"(saddr), "l"(gaddr));
}
__device__ __forceinline__ void cp_commit() {
    asm volatile("cp.async.commit_group;\n" ::: "memory");
}

// ---------------------------------------------------------------------------
// Attention: one warp = 2 query rows of one (b,h); q rows in registers.
// K streamed through a 3-stage cp.async ring (one __syncthreads per tile).
// Online exact top-32 per row (warp-distributed, REDUX-min), then softmax
// over the 32 survivors and a 32-row V gather.
// Block = 256 threads (8 warps -> 16 rows). Grid = (S/16, H, B).
// ---------------------------------------------------------------------------
__global__ __launch_bounds__(256) void attn_kernel(float* __restrict__ out)
{
    const int b    = blockIdx.z;
    const int h    = blockIdx.y;
    const int warp = threadIdx.x >> 5;
    const int lane = threadIdx.x & 31;
    const int tid  = threadIdx.x;
    const int r0   = blockIdx.x * 16 + warp * 2;
    const int r1   = r0 + 1;

    __shared__ float4 ksh[3][32 * 16];   // 3-stage ring, xor-swizzled tiles

    const float4* Qp4 = (const float4*)g_Qp;
    const float4* Kp4 = (const float4*)g_Kp;
    const float4* Kbase = Kp4 + (size_t)b * NS * (ND / 4) + h * 16;

    // q rows in registers
    float4 q0[16], q1[16];
    {
        const float4* p0 = Qp4 + (size_t)(b * NS + r0) * (ND / 4) + h * (NDK / 4);
        const float4* p1 = Qp4 + (size_t)(b * NS + r1) * (ND / 4) + h * (NDK / 4);
#pragma unroll
        for (int i = 0; i < 16; i++) { q0[i] = p0[i]; q1[i] = p1[i]; }
    }

    // per-tile cp.async mapping: this thread fills 2 float4 slots
    const int j0 = tid >> 4, i0 = tid & 15;                 // slot 0
    const int j1 = (tid + 256) >> 4, i1 = tid & 15;         // slot 1
    const unsigned sbase = (unsigned)__cvta_generic_to_shared(&ksh[0][0]);
    const unsigned soff0 = ((j0 << 4) | (i0 ^ (j0 & 7))) * 16u;
    const unsigned soff1 = ((j1 << 4) | (i1 ^ (j1 & 7))) * 16u;

    // prefetch tiles 0 and 1
#pragma unroll
    for (int p = 0; p < 2; p++) {
        const unsigned sb = sbase + (unsigned)(p * 512 * 16);
        cp_async16(sb + soff0, Kbase + (size_t)(p * 32 + j0) * (ND / 4) + i0);
        cp_async16(sb + soff1, Kbase + (size_t)(p * 32 + j1) * (ND / 4) + i1);
        cp_commit();
    }

    unsigned lu0 = 0, lu1 = 0;          // list entries (u-space), one per lane
    int lidx0 = 0, lidx1 = 0;
    unsigned umin0 = 0, umin1 = 0;
    int minlane0 = 0, minlane1 = 0;

    const int sw = lane & 7;

    for (int tile = 0; tile < NTILES; ++tile) {
        if (tile < NTILES - 1)
            asm volatile("cp.async.wait_group 1;\n" ::: "memory");
        else
            asm volatile("cp.async.wait_group 0;\n" ::: "memory");
        __syncthreads();

        // prefetch tile+2 into ring slot (reused from tile-1's compute,
        // which the barrier above has fully retired)
        if (tile + 2 < NTILES) {
            const unsigned sb = sbase + (unsigned)(((tile + 2) % 3) * 512 * 16);
            cp_async16(sb + soff0, Kbase + (size_t)((tile + 2) * 32 + j0) * (ND / 4) + i0);
            cp_async16(sb + soff1, Kbase + (size_t)((tile + 2) * 32 + j1) * (ND / 4) + i1);
            cp_commit();
        }

        const float4* kt = ksh[tile % 3];

        // lane scores k-row (tile*32 + lane) against q0 and q1
        float a0x = 0.f, a0y = 0.f, a0z = 0.f, a0w = 0.f;
        float a1x = 0.f, a1y = 0.f, a1z = 0.f, a1w = 0.f;
#pragma unroll
        for (int i = 0; i < 16; i++) {
            const float4 kv = kt[(lane << 4) | (i ^ sw)];
            a0x += q0[i].x * kv.x; a0y += q0[i].y * kv.y;
            a0z += q0[i].z * kv.z; a0w += q0[i].w * kv.w;
            a1x += q1[i].x * kv.x; a1y += q1[i].y * kv.y;
            a1z += q1[i].z * kv.z; a1w += q1[i].w * kv.w;
        }
        const float s0 = ((a0x + a0y) + (a0z + a0w)) * 0.125f;
        const float s1 = ((a1x + a1y) + (a1z + a1w)) * 0.125f;
        const unsigned us0 = f2mono(s0);
        const unsigned us1 = f2mono(s1);
        const int idx = tile * 32 + lane;

        if (tile == 0) {
            // first 32 scores ARE the initial top-32
            lu0 = us0; lidx0 = idx;
            lu1 = us1; lidx1 = idx;
            umin0 = __reduce_min_sync(0xffffffffu, lu0);
            minlane0 = __ffs(__ballot_sync(0xffffffffu, lu0 == umin0)) - 1;
            umin1 = __reduce_min_sync(0xffffffffu, lu1);
            minlane1 = __ffs(__ballot_sync(0xffffffffu, lu1 == umin1)) - 1;
        } else {
            insert_u(us0, idx, lane, lu0, lidx0, umin0, minlane0);
            insert_u(us1, idx, lane, lu1, lidx1, umin1, minlane1);
        }
    }

    // softmax over the 32 survivors (== reference masked softmax: masked
    // entries contribute exp(-1e9 - max) == 0 in fp32)
    const float lval0 = mono2f(lu0);
    const float lval1 = mono2f(lu1);

    const float m0 = warp_max(lval0);
    const float e0 = __expf(lval0 - m0);
    const float w0 = e0 / warp_sum(e0);

    const float m1 = warp_max(lval1);
    const float e1 = __expf(lval1 - m1);
    const float w1 = e1 / warp_sum(e1);

    // AV gather: lane owns output dims (2*lane, 2*lane+1)
    const float* Vb = g_Vp + (size_t)b * NS * ND + h * NDK + lane * 2;
    float2 acc0 = make_float2(0.f, 0.f);
    float2 acc1 = make_float2(0.f, 0.f);
#pragma unroll
    for (int t = 0; t < 32; t++) {
        const int   vi0 = __shfl_sync(0xffffffffu, lidx0, t);
        const float wt0 = __shfl_sync(0xffffffffu, w0, t);
        const float2 v0 = *(const float2*)(Vb + (size_t)vi0 * ND);
        acc0.x += wt0 * v0.x; acc0.y += wt0 * v0.y;

        const int   vi1 = __shfl_sync(0xffffffffu, lidx1, t);
        const float wt1 = __shfl_sync(0xffffffffu, w1, t);
        const float2 v1 = *(const float2*)(Vb + (size_t)vi1 * ND);
        acc1.x += wt1 * v1.x; acc1.y += wt1 * v1.y;
    }

    *(float2*)(out + (size_t)(b * NS + r0) * ND + h * NDK + lane * 2) = acc0;
    *(float2*)(out + (size_t)(b * NS + r1) * ND + h * NDK + lane * 2) = acc1;
}

// ---------------------------------------------------------------------------
extern "C" void kernel_launch(void* const* d_in, const int* in_sizes, int n_in,
                              void* d_out, int out_size)
{
    const float* query = (const float*)d_in[0];
    const float* key   = (const float*)d_in[1];
    const float* value = (const float*)d_in[2];
    const float* Wq    = (const float*)d_in[3];
    const float* bq    = (const float*)d_in[4];
    const float* Wk    = (const float*)d_in[5];
    const float* bk    = (const float*)d_in[6];
    const float* Wv    = (const float*)d_in[7];
    const float* bv    = (const float*)d_in[8];
    float* out = (float*)d_out;

    dim3 pgrid(ND / 128, (NB * NS) / 128, 3);
    proj_kernel<<<pgrid, 256>>>(query, Wq, bq, key, Wk, bk, value, Wv, bv);

    dim3 agrid(NS / 16, NH, NB);
    attn_kernel<<<agrid, 256>>>(out);
}

// round 5
// speedup vs baseline: 2.1242x; 1.2918x over previous
#include <cuda_runtime.h>
#include <math.h>

#define NB 2
#define NS 2048
#define ND 1024
#define NH 16
#define NDK 64
#define NTOPK 32
#define NTILES (NS / 32)

// Scratch for projected Q/K/V, layout [B, S, D] fp32 (head h = cols h*64..h*64+63)
__device__ float g_Qp[NB * NS * ND];
__device__ float g_Kp[NB * NS * ND];
__device__ float g_Vp[NB * NS * ND];

// ---------------------------------------------------------------------------
// Projection GEMM: C[M,N] = relu(A[M,K] @ W[K,N] + bias), M=4096, N=K=1024.
// (at fp32 FFMA floor ~0.65ms; left unchanged this round)
// ---------------------------------------------------------------------------
__global__ __launch_bounds__(256, 1) void proj_kernel(
    const float* __restrict__ X0, const float* __restrict__ W0, const float* __restrict__ B0,
    const float* __restrict__ X1, const float* __restrict__ W1, const float* __restrict__ B1,
    const float* __restrict__ X2, const float* __restrict__ W2, const float* __restrict__ B2)
{
    const int N = ND, K = ND;
    const int z = blockIdx.z;
    const float* A    = (z == 0) ? X0 : (z == 1) ? X1 : X2;
    const float* W    = (z == 0) ? W0 : (z == 1) ? W1 : W2;
    const float* bias = (z == 0) ? B0 : (z == 1) ? B1 : B2;
    float* C          = (z == 0) ? g_Qp : (z == 1) ? g_Kp : g_Vp;

    __shared__ float As[8][128];
    __shared__ float Bs[8][128];

    const int tid = threadIdx.x;
    const int tx = tid & 15;
    const int ty = tid >> 4;
    const int brow = blockIdx.y * 128;
    const int bcol = blockIdx.x * 128;

    const int lr = tid >> 1;
    const int lc = (tid & 1) << 2;
    const int wr = tid >> 5;
    const int wc = (tid & 31) << 2;

    float acc[8][8];
#pragma unroll
    for (int i = 0; i < 8; i++)
#pragma unroll
        for (int j = 0; j < 8; j++) acc[i][j] = 0.0f;

    const float* Aptr = A + (size_t)(brow + lr) * K + lc;
    const float* Wptr = W + (size_t)wr * N + bcol + wc;

    for (int k0 = 0; k0 < K; k0 += 8) {
        float4 a = *(const float4*)(Aptr + k0);
        float4 w = *(const float4*)(Wptr + (size_t)k0 * N);
        __syncthreads();
        As[lc + 0][lr] = a.x;
        As[lc + 1][lr] = a.y;
        As[lc + 2][lr] = a.z;
        As[lc + 3][lr] = a.w;
        *(float4*)&Bs[wr][wc] = w;
        __syncthreads();
#pragma unroll
        for (int k = 0; k < 8; k++) {
            float4 a0 = *(const float4*)&As[k][ty * 8];
            float4 a1 = *(const float4*)&As[k][ty * 8 + 4];
            float4 b0 = *(const float4*)&Bs[k][tx * 8];
            float4 b1 = *(const float4*)&Bs[k][tx * 8 + 4];
            float ar[8] = {a0.x, a0.y, a0.z, a0.w, a1.x, a1.y, a1.z, a1.w};
            float br[8] = {b0.x, b0.y, b0.z, b0.w, b1.x, b1.y, b1.z, b1.w};
#pragma unroll
            for (int i = 0; i < 8; i++)
#pragma unroll
                for (int j = 0; j < 8; j++)
                    acc[i][j] += ar[i] * br[j];
        }
    }

#pragma unroll
    for (int i = 0; i < 8; i++) {
        const int r = brow + ty * 8 + i;
        float* crow = C + (size_t)r * N + bcol + tx * 8;
#pragma unroll
        for (int j = 0; j < 8; j += 4) {
            const int c = bcol + tx * 8 + j;
            float4 v;
            v.x = fmaxf(acc[i][j + 0] + bias[c + 0], 0.0f);
            v.y = fmaxf(acc[i][j + 1] + bias[c + 1], 0.0f);
            v.z = fmaxf(acc[i][j + 2] + bias[c + 2], 0.0f);
            v.w = fmaxf(acc[i][j + 3] + bias[c + 3], 0.0f);
            *(float4*)(crow + j) = v;
        }
    }
}

// ---------------------------------------------------------------------------
// Helpers
// ---------------------------------------------------------------------------
__device__ __forceinline__ float warp_max(float v) {
#pragma unroll
    for (int off = 16; off > 0; off >>= 1)
        v = fmaxf(v, __shfl_xor_sync(0xffffffffu, v, off));
    return v;
}

__device__ __forceinline__ float warp_sum(float v) {
#pragma unroll
    for (int off = 16; off > 0; off >>= 1)
        v += __shfl_xor_sync(0xffffffffu, v, off);
    return v;
}

// Monotone float->uint transform: u-order == float-order (finite values).
__device__ __forceinline__ unsigned f2mono(float f) {
    unsigned b = __float_as_uint(f);
    return (b & 0x80000000u) ? ~b : (b | 0x80000000u);
}
__device__ __forceinline__ float mono2f(unsigned u) {
    unsigned b = (u & 0x80000000u) ? (u ^ 0x80000000u) : ~u;
    return __uint_as_float(b);
}

// Packed dual-FMA: acc.{lo,hi} += a.{lo,hi} * b.{lo,hi}  (one FFMA2 inst)
__device__ __forceinline__ void ffma2(unsigned long long& acc,
                                      unsigned long long a,
                                      unsigned long long b) {
    asm("fma.rn.f32x2 %0, %1, %2, %0;" : "+l"(acc) : "l"(a), "l"(b));
}

union F4U2 { float4 f; unsigned long long u[2]; };

// Insert one candidate-per-lane batch into the warp-distributed top-32 list.
// Strict '>' keeps earliest (lowest index) on ties, matching jax.lax.top_k.
__device__ __forceinline__ void insert_u(unsigned us, int idx, int lane,
                                         unsigned& lu, int& lidx,
                                         unsigned& umin, int& minlane)
{
    unsigned bal = __ballot_sync(0xffffffffu, us > umin);
    while (bal) {
        const int src = __ffs(bal) - 1;
        bal &= bal - 1;
        const unsigned uv = __shfl_sync(0xffffffffu, us, src);
        const int      vi = __shfl_sync(0xffffffffu, idx, src);
        if (uv > umin) {               // umin warp-uniform -> uniform branch
            if (lane == minlane) { lu = uv; lidx = vi; }
            umin = __reduce_min_sync(0xffffffffu, lu);
            minlane = __ffs(__ballot_sync(0xffffffffu, lu == umin)) - 1;
        }
    }
}

__device__ __forceinline__ void cp_async16(unsigned saddr, const void* gaddr) {
    asm volatile("cp.async.cg.shared.global [%0], [%1], 16;\n"
                 :: "r"(saddr), "l"(gaddr));
}
__device__ __forceinline__ void cp_commit() {
    asm volatile("cp.async.commit_group;\n" ::: "memory");
}

// ---------------------------------------------------------------------------
// Attention: one warp = 2 query rows (q packed as f32x2 in registers).
// Block = 128 threads (4 warps -> 8 rows), 3 CTAs/SM for latency hiding.
// K streamed via 3-stage cp.async ring. Scores via packed fma.rn.f32x2.
// Online exact top-32 per row, softmax over survivors, 32-row V gather.
// Grid = (S/8, H, B).
// ---------------------------------------------------------------------------
__global__ __launch_bounds__(128, 3) void attn_kernel(float* __restrict__ out)
{
    const int b    = blockIdx.z;
    const int h    = blockIdx.y;
    const int warp = threadIdx.x >> 5;
    const int lane = threadIdx.x & 31;
    const int tid  = threadIdx.x;
    const int r0   = blockIdx.x * 8 + warp * 2;
    const int r1   = r0 + 1;

    __shared__ float4 ksh[3][32 * 16];   // 3-stage ring, xor-swizzled tiles

    const float4* Qp4 = (const float4*)g_Qp;
    const float4* Kp4 = (const float4*)g_Kp;
    const float4* Kbase = Kp4 + (size_t)b * NS * (ND / 4) + h * 16;

    // q rows in registers, packed as f32x2 pairs (32 ULL per row)
    unsigned long long q0p[32], q1p[32];
    {
        const float4* p0 = Qp4 + (size_t)(b * NS + r0) * (ND / 4) + h * (NDK / 4);
        const float4* p1 = Qp4 + (size_t)(b * NS + r1) * (ND / 4) + h * (NDK / 4);
#pragma unroll
        for (int i = 0; i < 16; i++) {
            F4U2 c0, c1;
            c0.f = p0[i]; c1.f = p1[i];
            q0p[2 * i] = c0.u[0]; q0p[2 * i + 1] = c0.u[1];
            q1p[2 * i] = c1.u[0]; q1p[2 * i + 1] = c1.u[1];
        }
    }

    // per-tile cp.async mapping: 512 float4 slots / 128 threads = 4 each
    unsigned soff[4];
    int jrow[4];
#pragma unroll
    for (int k = 0; k < 4; k++) {
        const int f = tid + k * 128;
        const int j = f >> 4, i = f & 15;
        jrow[k] = j;
        soff[k] = ((j << 4) | (i ^ (j & 7))) * 16u;
    }
    const unsigned sbase = (unsigned)__cvta_generic_to_shared(&ksh[0][0]);

    // prefetch tiles 0 and 1
#pragma unroll
    for (int p = 0; p < 2; p++) {
        const unsigned sb = sbase + (unsigned)(p * 512 * 16);
#pragma unroll
        for (int k = 0; k < 4; k++)
            cp_async16(sb + soff[k],
                       Kbase + (size_t)(p * 32 + jrow[k]) * (ND / 4) + ((tid + k * 128) & 15));
        cp_commit();
    }

    unsigned lu0 = 0, lu1 = 0;          // list entries (u-space), one per lane
    int lidx0 = 0, lidx1 = 0;
    unsigned umin0 = 0, umin1 = 0;
    int minlane0 = 0, minlane1 = 0;

    const int sw = lane & 7;

    for (int tile = 0; tile < NTILES; ++tile) {
        if (tile < NTILES - 1)
            asm volatile("cp.async.wait_group 1;\n" ::: "memory");
        else
            asm volatile("cp.async.wait_group 0;\n" ::: "memory");
        __syncthreads();

        if (tile + 2 < NTILES) {
            const unsigned sb = sbase + (unsigned)(((tile + 2) % 3) * 512 * 16);
#pragma unroll
            for (int k = 0; k < 4; k++)
                cp_async16(sb + soff[k],
                           Kbase + (size_t)((tile + 2) * 32 + jrow[k]) * (ND / 4) + ((tid + k * 128) & 15));
            cp_commit();
        }

        const float4* kt = ksh[tile % 3];

        // lane scores k-row (tile*32 + lane) against q0 and q1 via FFMA2
        unsigned long long a00 = 0, a01 = 0, a10 = 0, a11 = 0;  // packed (0,0) accums
#pragma unroll
        for (int i = 0; i < 16; i++) {
            F4U2 kv;
            kv.f = kt[(lane << 4) | (i ^ sw)];
            ffma2(a00, q0p[2 * i],     kv.u[0]);
            ffma2(a01, q0p[2 * i + 1], kv.u[1]);
            ffma2(a10, q1p[2 * i],     kv.u[0]);
            ffma2(a11, q1p[2 * i + 1], kv.u[1]);
        }
        float2 f00 = *(float2*)&a00, f01 = *(float2*)&a01;
        float2 f10 = *(float2*)&a10, f11 = *(float2*)&a11;
        const float s0 = ((f00.x + f00.y) + (f01.x + f01.y)) * 0.125f;
        const float s1 = ((f10.x + f10.y) + (f11.x + f11.y)) * 0.125f;
        const unsigned us0 = f2mono(s0);
        const unsigned us1 = f2mono(s1);
        const int idx = tile * 32 + lane;

        if (tile == 0) {
            lu0 = us0; lidx0 = idx;
            lu1 = us1; lidx1 = idx;
            umin0 = __reduce_min_sync(0xffffffffu, lu0);
            minlane0 = __ffs(__ballot_sync(0xffffffffu, lu0 == umin0)) - 1;
            umin1 = __reduce_min_sync(0xffffffffu, lu1);
            minlane1 = __ffs(__ballot_sync(0xffffffffu, lu1 == umin1)) - 1;
        } else {
            insert_u(us0, idx, lane, lu0, lidx0, umin0, minlane0);
            insert_u(us1, idx, lane, lu1, lidx1, umin1, minlane1);
        }
    }

    // softmax over the 32 survivors (== reference masked softmax)
    const float lval0 = mono2f(lu0);
    const float lval1 = mono2f(lu1);

    const float m0 = warp_max(lval0);
    const float e0 = __expf(lval0 - m0);
    const float w0 = e0 / warp_sum(e0);

    const float m1 = warp_max(lval1);
    const float e1 = __expf(lval1 - m1);
    const float w1 = e1 / warp_sum(e1);

    // AV gather: lane owns output dims (2*lane, 2*lane+1)
    const float* Vb = g_Vp + (size_t)b * NS * ND + h * NDK + lane * 2;
    float2 acc0 = make_float2(0.f, 0.f);
    float2 acc1 = make_float2(0.f, 0.f);
#pragma unroll
    for (int t = 0; t < 32; t++) {
        const int   vi0 = __shfl_sync(0xffffffffu, lidx0, t);
        const float wt0 = __shfl_sync(0xffffffffu, w0, t);
        const float2 v0 = *(const float2*)(Vb + (size_t)vi0 * ND);
        acc0.x += wt0 * v0.x; acc0.y += wt0 * v0.y;

        const int   vi1 = __shfl_sync(0xffffffffu, lidx1, t);
        const float wt1 = __shfl_sync(0xffffffffu, w1, t);
        const float2 v1 = *(const float2*)(Vb + (size_t)vi1 * ND);
        acc1.x += wt1 * v1.x; acc1.y += wt1 * v1.y;
    }

    *(float2*)(out + (size_t)(b * NS + r0) * ND + h * NDK + lane * 2) = acc0;
    *(float2*)(out + (size_t)(b * NS + r1) * ND + h * NDK + lane * 2) = acc1;
}

// ---------------------------------------------------------------------------
extern "C" void kernel_launch(void* const* d_in, const int* in_sizes, int n_in,
                              void* d_out, int out_size)
{
    const float* query = (const float*)d_in[0];
    const float* key   = (const float*)d_in[1];
    const float* value = (const float*)d_in[2];
    const float* Wq    = (const float*)d_in[3];
    const float* bq    = (const float*)d_in[4];
    const float* Wk    = (const float*)d_in[5];
    const float* bk    = (const float*)d_in[6];
    const float* Wv    = (const float*)d_in[7];
    const float* bv    = (const float*)d_in[8];
    float* out = (float*)d_out;

    dim3 pgrid(ND / 128, (NB * NS) / 128, 3);
    proj_kernel<<<pgrid, 256>>>(query, Wq, bq, key, Wk, bk, value, Wv, bv);

    dim3 agrid(NS / 8, NH, NB);
    attn_kernel<<<agrid, 128>>>(out);
}

// round 6
// speedup vs baseline: 3.1446x; 1.4804x over previous
#include <cuda_runtime.h>
#include <math.h>

#define NB 2
#define NS 2048
#define ND 1024
#define NH 16
#define NDK 64

// Scratch: projected Q/K/V [B,S,D] fp32 (head h = cols h*64..h*64+63),
// plus full score matrix in order-preserving mono-u32 [BH][S][S] (512 MB).
__device__ float g_Qp[NB * NS * ND];
__device__ float g_Kp[NB * NS * ND];
__device__ float g_Vp[NB * NS * ND];
__device__ unsigned g_S[(size_t)NB * NH * NS * NS];

// ---------------------------------------------------------------------------
// Helpers
// ---------------------------------------------------------------------------
__device__ __forceinline__ float warp_max(float v) {
#pragma unroll
    for (int off = 16; off > 0; off >>= 1)
        v = fmaxf(v, __shfl_xor_sync(0xffffffffu, v, off));
    return v;
}
__device__ __forceinline__ float warp_sum(float v) {
#pragma unroll
    for (int off = 16; off > 0; off >>= 1)
        v += __shfl_xor_sync(0xffffffffu, v, off);
    return v;
}
// Monotone float<->uint transform: u-order == float-order (finite values).
__device__ __forceinline__ unsigned f2mono(float f) {
    unsigned b = __float_as_uint(f);
    return (b & 0x80000000u) ? ~b : (b | 0x80000000u);
}
__device__ __forceinline__ float mono2f(unsigned u) {
    unsigned b = (u & 0x80000000u) ? (u ^ 0x80000000u) : ~u;
    return __uint_as_float(b);
}
// Packed dual-FMA: acc.{lo,hi} += a.{lo,hi} * b.{lo,hi}
__device__ __forceinline__ void ffma2(unsigned long long& acc,
                                      unsigned long long a,
                                      unsigned long long b) {
    asm("fma.rn.f32x2 %0, %1, %2, %0;" : "+l"(acc) : "l"(a), "l"(b));
}
// Duplicate a float into both halves of a packed f32x2
__device__ __forceinline__ unsigned long long dup2(float x) {
    unsigned long long r;
    asm("mov.b64 %0, {%1, %1};" : "=l"(r) : "f"(x));
    return r;
}
union F4U2 { float4 f; unsigned long long u[2]; float s[4]; };

// ---------------------------------------------------------------------------
// Projection GEMM (FFMA2): C = relu(A @ W + bias), M=4096, N=K=1024, x3.
// ---------------------------------------------------------------------------
__global__ __launch_bounds__(256, 2) void proj_kernel(
    const float* __restrict__ X0, const float* __restrict__ W0, const float* __restrict__ B0,
    const float* __restrict__ X1, const float* __restrict__ W1, const float* __restrict__ B1,
    const float* __restrict__ X2, const float* __restrict__ W2, const float* __restrict__ B2)
{
    const int N = ND, K = ND;
    const int z = blockIdx.z;
    const float* A    = (z == 0) ? X0 : (z == 1) ? X1 : X2;
    const float* W    = (z == 0) ? W0 : (z == 1) ? W1 : W2;
    const float* bias = (z == 0) ? B0 : (z == 1) ? B1 : B2;
    float* C          = (z == 0) ? g_Qp : (z == 1) ? g_Kp : g_Vp;

    __shared__ float As[8][128];
    __shared__ float Bs[8][128];

    const int tid = threadIdx.x;
    const int tx = tid & 15;
    const int ty = tid >> 4;
    const int brow = blockIdx.y * 128;
    const int bcol = blockIdx.x * 128;

    const int lr = tid >> 1;
    const int lc = (tid & 1) << 2;
    const int wr = tid >> 5;
    const int wc = (tid & 31) << 2;

    unsigned long long accp[8][4];
#pragma unroll
    for (int i = 0; i < 8; i++)
#pragma unroll
        for (int p = 0; p < 4; p++) accp[i][p] = 0ull;

    const float* Aptr = A + (size_t)(brow + lr) * K + lc;
    const float* Wptr = W + (size_t)wr * N + bcol + wc;

    for (int k0 = 0; k0 < K; k0 += 8) {
        float4 a = *(const float4*)(Aptr + k0);
        float4 w = *(const float4*)(Wptr + (size_t)k0 * N);
        __syncthreads();
        As[lc + 0][lr] = a.x;
        As[lc + 1][lr] = a.y;
        As[lc + 2][lr] = a.z;
        As[lc + 3][lr] = a.w;
        *(float4*)&Bs[wr][wc] = w;
        __syncthreads();
#pragma unroll
        for (int k = 0; k < 8; k++) {
            float4 a0 = *(const float4*)&As[k][ty * 8];
            float4 a1 = *(const float4*)&As[k][ty * 8 + 4];
            F4U2 b0, b1;
            b0.f = *(const float4*)&Bs[k][tx * 8];
            b1.f = *(const float4*)&Bs[k][tx * 8 + 4];
            unsigned long long bp[4] = {b0.u[0], b0.u[1], b1.u[0], b1.u[1]};
            float ar[8] = {a0.x, a0.y, a0.z, a0.w, a1.x, a1.y, a1.z, a1.w};
#pragma unroll
            for (int i = 0; i < 8; i++) {
                unsigned long long ad = dup2(ar[i]);
#pragma unroll
                for (int p = 0; p < 4; p++) ffma2(accp[i][p], ad, bp[p]);
            }
        }
    }

#pragma unroll
    for (int i = 0; i < 8; i++) {
        const int r = brow + ty * 8 + i;
        float* crow = C + (size_t)r * N + bcol + tx * 8;
        const float2* ap = (const float2*)&accp[i][0];
#pragma unroll
        for (int j = 0; j < 8; j += 4) {
            const int c = bcol + tx * 8 + j;
            float2 p0 = ap[j / 2], p1 = ap[j / 2 + 1];
            float4 v;
            v.x = fmaxf(p0.x + bias[c + 0], 0.0f);
            v.y = fmaxf(p0.y + bias[c + 1], 0.0f);
            v.z = fmaxf(p1.x + bias[c + 2], 0.0f);
            v.w = fmaxf(p1.y + bias[c + 3], 0.0f);
            *(float4*)(crow + j) = v;
        }
    }
}

// ---------------------------------------------------------------------------
// Phase A: score GEMM. Per (b,h): S = (Qh @ Kh^T) / 8, written as mono-u32.
// 128x128 tile / CTA, 8x8 micro, K=64 in two 32-wide smem phases.
// Grid = (16, 16, 32).
// ---------------------------------------------------------------------------
#define SPAD 132
__global__ __launch_bounds__(256, 2) void score_kernel()
{
    __shared__ float As[32][SPAD];   // As[k][m]
    __shared__ float Bs[32][SPAD];   // Bs[k][n]

    const int bh = blockIdx.z;
    const int b = bh >> 4, h = bh & 15;
    const int brow = blockIdx.y * 128;
    const int bcol = blockIdx.x * 128;
    const int tid = threadIdx.x;
    const int tx = tid & 15;
    const int ty = tid >> 4;

    const float* Qb = g_Qp + (size_t)b * NS * ND + h * NDK;
    const float* Kb = g_Kp + (size_t)b * NS * ND + h * NDK;

    unsigned long long accp[8][4];
#pragma unroll
    for (int i = 0; i < 8; i++)
#pragma unroll
        for (int p = 0; p < 4; p++) accp[i][p] = 0ull;

    const int d4 = tid & 7;      // float4 index within 32-wide k chunk
    const int rr = tid >> 3;     // 0..31

    for (int kc = 0; kc < 2; kc++) {
        __syncthreads();
#pragma unroll
        for (int c = 0; c < 4; c++) {
            const int r = rr + c * 32;
            float4 qa = *(const float4*)(Qb + (size_t)(brow + r) * ND + kc * 32 + d4 * 4);
            As[d4 * 4 + 0][r] = qa.x;
            As[d4 * 4 + 1][r] = qa.y;
            As[d4 * 4 + 2][r] = qa.z;
            As[d4 * 4 + 3][r] = qa.w;
            float4 kb = *(const float4*)(Kb + (size_t)(bcol + r) * ND + kc * 32 + d4 * 4);
            Bs[d4 * 4 + 0][r] = kb.x;
            Bs[d4 * 4 + 1][r] = kb.y;
            Bs[d4 * 4 + 2][r] = kb.z;
            Bs[d4 * 4 + 3][r] = kb.w;
        }
        __syncthreads();
#pragma unroll 8
        for (int k = 0; k < 32; k++) {
            float4 a0 = *(const float4*)&As[k][ty * 8];
            float4 a1 = *(const float4*)&As[k][ty * 8 + 4];
            F4U2 b0, b1;
            b0.f = *(const float4*)&Bs[k][tx * 8];
            b1.f = *(const float4*)&Bs[k][tx * 8 + 4];
            unsigned long long bp[4] = {b0.u[0], b0.u[1], b1.u[0], b1.u[1]};
            float ar[8] = {a0.x, a0.y, a0.z, a0.w, a1.x, a1.y, a1.z, a1.w};
#pragma unroll
            for (int i = 0; i < 8; i++) {
                unsigned long long ad = dup2(ar[i]);
#pragma unroll
                for (int p = 0; p < 4; p++) ffma2(accp[i][p], ad, bp[p]);
            }
        }
    }

    // epilogue: scale by 1/8, mono-transform, store u32
    unsigned* Sb = g_S + (size_t)bh * NS * NS;
#pragma unroll
    for (int i = 0; i < 8; i++) {
        const int row = brow + ty * 8 + i;
        unsigned* srow = Sb + (size_t)row * NS + bcol + tx * 8;
        const float2* ap = (const float2*)&accp[i][0];
        uint4 u0, u1;
        u0.x = f2mono(ap[0].x * 0.125f);
        u0.y = f2mono(ap[0].y * 0.125f);
        u0.z = f2mono(ap[1].x * 0.125f);
        u0.w = f2mono(ap[1].y * 0.125f);
        u1.x = f2mono(ap[2].x * 0.125f);
        u1.y = f2mono(ap[2].y * 0.125f);
        u1.z = f2mono(ap[3].x * 0.125f);
        u1.w = f2mono(ap[3].y * 0.125f);
        *(uint4*)(srow + 0) = u0;
        *(uint4*)(srow + 4) = u1;
    }
}

// ---------------------------------------------------------------------------
// Phase B: per (b,h,s) row — exact top-32 over the stored mono-u32 scores,
// softmax over survivors (exact fp32 via mono2f), V gather, output.
// One warp per row; CTA = 8 warps; grid = 65536/8 = 8192 CTAs.
// Batches are processed in ascending index order -> tie semantics match
// jax.lax.top_k (earliest index wins on equal value).
// ---------------------------------------------------------------------------
__global__ __launch_bounds__(256) void select_kernel(float* __restrict__ out)
{
    const int warp = threadIdx.x >> 5;
    const int lane = threadIdx.x & 31;
    const int job = blockIdx.x * 8 + warp;   // 0..65535
    const int bh = job >> 11;
    const int s  = job & 2047;
    const int b = bh >> 4, h = bh & 15;

    const unsigned* srow = g_S + (size_t)bh * NS * NS + (size_t)s * NS;

    // init list from first 32 candidates
    unsigned lu = srow[lane];
    int lidx = lane;
    unsigned umin = __reduce_min_sync(0xffffffffu, lu);
    int minlane = __ffs(__ballot_sync(0xffffffffu, lu == umin)) - 1;

    unsigned unext = srow[32 + lane];
    for (int t = 1; t < 64; t++) {
        const unsigned u = unext;
        if (t < 63) unext = srow[(t + 1) * 32 + lane];
        const int idx = t * 32 + lane;

        unsigned bal = __ballot_sync(0xffffffffu, u > umin);
        while (bal) {
            const int src = __ffs(bal) - 1;
            bal &= bal - 1;
            const unsigned uv = __shfl_sync(0xffffffffu, u, src);
            const int      vi = __shfl_sync(0xffffffffu, idx, src);
            if (uv > umin) {             // umin warp-uniform -> uniform branch
                if (lane == minlane) { lu = uv; lidx = vi; }
                umin = __reduce_min_sync(0xffffffffu, lu);
                minlane = __ffs(__ballot_sync(0xffffffffu, lu == umin)) - 1;
            }
        }
    }

    // softmax over the 32 survivors (== reference masked softmax: masked
    // entries contribute exp(-1e9 - max) == 0 in fp32)
    const float lval = mono2f(lu);
    const float m = warp_max(lval);
    const float e = __expf(lval - m);
    const float w = e / warp_sum(e);

    // AV gather: lane owns output dims (2*lane, 2*lane+1)
    const float* Vb = g_Vp + (size_t)b * NS * ND + h * NDK + lane * 2;
    float2 acc = make_float2(0.f, 0.f);
#pragma unroll
    for (int t = 0; t < 32; t++) {
        const int   vi = __shfl_sync(0xffffffffu, lidx, t);
        const float wt = __shfl_sync(0xffffffffu, w, t);
        const float2 v = *(const float2*)(Vb + (size_t)vi * ND);
        acc.x += wt * v.x;
        acc.y += wt * v.y;
    }

    *(float2*)(out + (size_t)(b * NS + s) * ND + h * NDK + lane * 2) = acc;
}

// ---------------------------------------------------------------------------
extern "C" void kernel_launch(void* const* d_in, const int* in_sizes, int n_in,
                              void* d_out, int out_size)
{
    const float* query = (const float*)d_in[0];
    const float* key   = (const float*)d_in[1];
    const float* value = (const float*)d_in[2];
    const float* Wq    = (const float*)d_in[3];
    const float* bq    = (const float*)d_in[4];
    const float* Wk    = (const float*)d_in[5];
    const float* bk    = (const float*)d_in[6];
    const float* Wv    = (const float*)d_in[7];
    const float* bv    = (const float*)d_in[8];
    float* out = (float*)d_out;

    dim3 pgrid(ND / 128, (NB * NS) / 128, 3);
    proj_kernel<<<pgrid, 256>>>(query, Wq, bq, key, Wk, bk, value, Wv, bv);

    dim3 sgrid(NS / 128, NS / 128, NB * NH);
    score_kernel<<<sgrid, 256>>>();

    select_kernel<<<(NB * NH * NS) / 8, 256>>>(out);
}

// round 7
// speedup vs baseline: 3.8334x; 1.2190x over previous
#include <cuda_runtime.h>
#include <math.h>

#define NB 2
#define NS 2048
#define ND 1024
#define NH 16
#define NDK 64

// Scratch: projected Q/K/V [B,S,D] fp32 (head h = cols h*64..h*64+63),
// plus full score matrix in order-preserving mono-u32 [BH][S][S] (512 MB).
__device__ float g_Qp[NB * NS * ND];
__device__ float g_Kp[NB * NS * ND];
__device__ float g_Vp[NB * NS * ND];
__device__ unsigned g_S[(size_t)NB * NH * NS * NS];

// ---------------------------------------------------------------------------
// Helpers
// ---------------------------------------------------------------------------
__device__ __forceinline__ float warp_max(float v) {
#pragma unroll
    for (int off = 16; off > 0; off >>= 1)
        v = fmaxf(v, __shfl_xor_sync(0xffffffffu, v, off));
    return v;
}
__device__ __forceinline__ float warp_sum(float v) {
#pragma unroll
    for (int off = 16; off > 0; off >>= 1)
        v += __shfl_xor_sync(0xffffffffu, v, off);
    return v;
}
// Monotone float<->uint transform: u-order == float-order (finite values).
__device__ __forceinline__ unsigned f2mono(float f) {
    unsigned b = __float_as_uint(f);
    return (b & 0x80000000u) ? ~b : (b | 0x80000000u);
}
__device__ __forceinline__ float mono2f(unsigned u) {
    unsigned b = (u & 0x80000000u) ? (u ^ 0x80000000u) : ~u;
    return __uint_as_float(b);
}
// Packed dual-FMA: acc.{lo,hi} += a.{lo,hi} * b.{lo,hi}
__device__ __forceinline__ void ffma2(unsigned long long& acc,
                                      unsigned long long a,
                                      unsigned long long b) {
    asm("fma.rn.f32x2 %0, %1, %2, %0;" : "+l"(acc) : "l"(a), "l"(b));
}
// Duplicate a float into both halves of a packed f32x2
__device__ __forceinline__ unsigned long long dup2(float x) {
    unsigned long long r;
    asm("mov.b64 %0, {%1, %1};" : "=l"(r) : "f"(x));
    return r;
}
union F4U2 { float4 f; unsigned long long u[2]; float s[4]; };

// ---------------------------------------------------------------------------
// Projection GEMM (FFMA2): C = relu(A @ W + bias), M=4096, N=K=1024, x3.
// BK=16, double-buffered smem, ONE __syncthreads per k-step, LDG staged in
// registers during previous step's compute. Conflict-free microtile:
// thread covers rows {ty*4+i, 64+ty*4+i} and cols {tx*4+j, 64+tx*4+j}.
// ---------------------------------------------------------------------------
__global__ __launch_bounds__(256, 2) void proj_kernel(
    const float* __restrict__ X0, const float* __restrict__ W0, const float* __restrict__ B0,
    const float* __restrict__ X1, const float* __restrict__ W1, const float* __restrict__ B1,
    const float* __restrict__ X2, const float* __restrict__ W2, const float* __restrict__ B2)
{
    const int N = ND, K = ND;
    const int z = blockIdx.z;
    const float* A    = (z == 0) ? X0 : (z == 1) ? X1 : X2;
    const float* W    = (z == 0) ? W0 : (z == 1) ? W1 : W2;
    const float* bias = (z == 0) ? B0 : (z == 1) ? B1 : B2;
    float* C          = (z == 0) ? g_Qp : (z == 1) ? g_Kp : g_Vp;

    __shared__ float As[2][16][128];   // As[buf][k][m]
    __shared__ float Bs[2][16][128];   // Bs[buf][k][n]

    const int tid = threadIdx.x;
    const int tx = tid & 15;
    const int ty = tid >> 4;
    const int brow = blockIdx.y * 128;
    const int bcol = blockIdx.x * 128;

    // global load mapping
    const int ar = tid >> 1;            // A row within tile (0..127)
    const int ak = (tid & 1) << 3;      // A k-offset (0 or 8)
    const int wr = tid >> 4;            // W k-row within slab (0..15)
    const int wc = (tid & 15) << 3;     // W col (0..120)

    unsigned long long accp[8][4];
#pragma unroll
    for (int i = 0; i < 8; i++)
#pragma unroll
        for (int q = 0; q < 4; q++) accp[i][q] = 0ull;

    const float* Aptr = A + (size_t)(brow + ar) * K + ak;
    const float* Wptr = W + (size_t)wr * N + bcol + wc;

    float4 a0 = *(const float4*)(Aptr);
    float4 a1 = *(const float4*)(Aptr + 4);
    float4 w0 = *(const float4*)(Wptr);
    float4 w1 = *(const float4*)(Wptr + 4);

    int p = 0;
    for (int k0 = 0; k0 < K; k0 += 16) {
        // commit staged tile to buffer p (prev compute of p finished: we
        // passed the barrier of the previous iteration after computing it)
        As[p][ak + 0][ar] = a0.x;
        As[p][ak + 1][ar] = a0.y;
        As[p][ak + 2][ar] = a0.z;
        As[p][ak + 3][ar] = a0.w;
        As[p][ak + 4][ar] = a1.x;
        As[p][ak + 5][ar] = a1.y;
        As[p][ak + 6][ar] = a1.z;
        As[p][ak + 7][ar] = a1.w;
        *(float4*)&Bs[p][wr][wc] = w0;
        *(float4*)&Bs[p][wr][wc + 4] = w1;
        __syncthreads();
        // stage next tile (in flight during compute below)
        if (k0 + 16 < K) {
            a0 = *(const float4*)(Aptr + k0 + 16);
            a1 = *(const float4*)(Aptr + k0 + 20);
            w0 = *(const float4*)(Wptr + (size_t)(k0 + 16) * N);
            w1 = *(const float4*)(Wptr + (size_t)(k0 + 16) * N + 4);
        }
#pragma unroll
        for (int k = 0; k < 16; k++) {
            float4 av0 = *(const float4*)&As[p][k][ty * 4];
            float4 av1 = *(const float4*)&As[p][k][64 + ty * 4];
            F4U2 b0, b1;
            b0.f = *(const float4*)&Bs[p][k][tx * 4];
            b1.f = *(const float4*)&Bs[p][k][64 + tx * 4];
            unsigned long long bp[4] = {b0.u[0], b0.u[1], b1.u[0], b1.u[1]};
            float arr[8] = {av0.x, av0.y, av0.z, av0.w, av1.x, av1.y, av1.z, av1.w};
#pragma unroll
            for (int i = 0; i < 8; i++) {
                unsigned long long ad = dup2(arr[i]);
#pragma unroll
                for (int q = 0; q < 4; q++) ffma2(accp[i][q], ad, bp[q]);
            }
        }
        p ^= 1;
    }

#pragma unroll
    for (int i = 0; i < 8; i++) {
        const int r = brow + ((i < 4) ? (ty * 4 + i) : (64 + ty * 4 + (i - 4)));
        const float2* ap = (const float2*)&accp[i][0];
        {
            const int c = bcol + tx * 4;
            float4 v;
            v.x = fmaxf(ap[0].x + bias[c + 0], 0.0f);
            v.y = fmaxf(ap[0].y + bias[c + 1], 0.0f);
            v.z = fmaxf(ap[1].x + bias[c + 2], 0.0f);
            v.w = fmaxf(ap[1].y + bias[c + 3], 0.0f);
            *(float4*)(C + (size_t)r * N + c) = v;
        }
        {
            const int c = bcol + 64 + tx * 4;
            float4 v;
            v.x = fmaxf(ap[2].x + bias[c + 0], 0.0f);
            v.y = fmaxf(ap[2].y + bias[c + 1], 0.0f);
            v.z = fmaxf(ap[3].x + bias[c + 2], 0.0f);
            v.w = fmaxf(ap[3].y + bias[c + 3], 0.0f);
            *(float4*)(C + (size_t)r * N + c) = v;
        }
    }
}

// ---------------------------------------------------------------------------
// Phase A: score GEMM. Per (b,h): S = (Qh @ Kh^T) / 8, written as mono-u32.
// 128x128 tile / CTA, conflict-free split microtile, K=64 in two 32-wide
// smem phases. Grid = (16, 16, 32).
// ---------------------------------------------------------------------------
#define SPAD 132
__global__ __launch_bounds__(256, 2) void score_kernel()
{
    __shared__ float As[32][SPAD];   // As[k][m]
    __shared__ float Bs[32][SPAD];   // Bs[k][n]

    const int bh = blockIdx.z;
    const int b = bh >> 4, h = bh & 15;
    const int brow = blockIdx.y * 128;
    const int bcol = blockIdx.x * 128;
    const int tid = threadIdx.x;
    const int tx = tid & 15;
    const int ty = tid >> 4;

    const float* Qb = g_Qp + (size_t)b * NS * ND + h * NDK;
    const float* Kb = g_Kp + (size_t)b * NS * ND + h * NDK;

    unsigned long long accp[8][4];
#pragma unroll
    for (int i = 0; i < 8; i++)
#pragma unroll
        for (int q = 0; q < 4; q++) accp[i][q] = 0ull;

    const int d4 = tid & 7;      // float4 index within 32-wide k chunk
    const int rr = tid >> 3;     // 0..31

    for (int kc = 0; kc < 2; kc++) {
        __syncthreads();
#pragma unroll
        for (int c = 0; c < 4; c++) {
            const int r = rr + c * 32;
            float4 qa = *(const float4*)(Qb + (size_t)(brow + r) * ND + kc * 32 + d4 * 4);
            As[d4 * 4 + 0][r] = qa.x;
            As[d4 * 4 + 1][r] = qa.y;
            As[d4 * 4 + 2][r] = qa.z;
            As[d4 * 4 + 3][r] = qa.w;
            float4 kb = *(const float4*)(Kb + (size_t)(bcol + r) * ND + kc * 32 + d4 * 4);
            Bs[d4 * 4 + 0][r] = kb.x;
            Bs[d4 * 4 + 1][r] = kb.y;
            Bs[d4 * 4 + 2][r] = kb.z;
            Bs[d4 * 4 + 3][r] = kb.w;
        }
        __syncthreads();
#pragma unroll 8
        for (int k = 0; k < 32; k++) {
            float4 av0 = *(const float4*)&As[k][ty * 4];
            float4 av1 = *(const float4*)&As[k][64 + ty * 4];
            F4U2 b0, b1;
            b0.f = *(const float4*)&Bs[k][tx * 4];
            b1.f = *(const float4*)&Bs[k][64 + tx * 4];
            unsigned long long bp[4] = {b0.u[0], b0.u[1], b1.u[0], b1.u[1]};
            float arr[8] = {av0.x, av0.y, av0.z, av0.w, av1.x, av1.y, av1.z, av1.w};
#pragma unroll
            for (int i = 0; i < 8; i++) {
                unsigned long long ad = dup2(arr[i]);
#pragma unroll
                for (int q = 0; q < 4; q++) ffma2(accp[i][q], ad, bp[q]);
            }
        }
    }

    // epilogue: scale by 1/8, mono-transform, store u32
    unsigned* Sb = g_S + (size_t)bh * NS * NS;
#pragma unroll
    for (int i = 0; i < 8; i++) {
        const int row = brow + ((i < 4) ? (ty * 4 + i) : (64 + ty * 4 + (i - 4)));
        unsigned* srow = Sb + (size_t)row * NS;
        const float2* ap = (const float2*)&accp[i][0];
        uint4 u0, u1;
        u0.x = f2mono(ap[0].x * 0.125f);
        u0.y = f2mono(ap[0].y * 0.125f);
        u0.z = f2mono(ap[1].x * 0.125f);
        u0.w = f2mono(ap[1].y * 0.125f);
        u1.x = f2mono(ap[2].x * 0.125f);
        u1.y = f2mono(ap[2].y * 0.125f);
        u1.z = f2mono(ap[3].x * 0.125f);
        u1.w = f2mono(ap[3].y * 0.125f);
        *(uint4*)(srow + bcol + tx * 4) = u0;
        *(uint4*)(srow + bcol + 64 + tx * 4) = u1;
    }
}

// ---------------------------------------------------------------------------
// Phase B: per (b,h,s) row — exact top-32 over the stored mono-u32 scores,
// softmax over survivors (exact fp32 via mono2f), V gather, output.
// One warp per row; 4-deep prefetch ring on the score stream.
// ---------------------------------------------------------------------------
__global__ __launch_bounds__(256) void select_kernel(float* __restrict__ out)
{
    const int warp = threadIdx.x >> 5;
    const int lane = threadIdx.x & 31;
    const int job = blockIdx.x * 8 + warp;   // 0..65535
    const int bh = job >> 11;
    const int s  = job & 2047;
    const int b = bh >> 4, h = bh & 15;

    const unsigned* srow = g_S + (size_t)bh * NS * NS + (size_t)s * NS;

    // init list from first 32 candidates
    unsigned lu = srow[lane];
    int lidx = lane;
    unsigned umin = __reduce_min_sync(0xffffffffu, lu);
    int minlane = __ffs(__ballot_sync(0xffffffffu, lu == umin)) - 1;

    // 4-deep prefetch ring
    unsigned nxt[4];
#pragma unroll
    for (int j = 0; j < 4; j++) nxt[j] = srow[(1 + j) * 32 + lane];

#pragma unroll 4
    for (int t = 1; t < 64; t++) {
        const unsigned u = nxt[(t - 1) & 3];
        if (t + 4 < 64) nxt[(t - 1) & 3] = srow[(t + 4) * 32 + lane];
        const int idx = t * 32 + lane;

        unsigned bal = __ballot_sync(0xffffffffu, u > umin);
        while (bal) {
            const int src = __ffs(bal) - 1;
            bal &= bal - 1;
            const unsigned uv = __shfl_sync(0xffffffffu, u, src);
            const int      vi = __shfl_sync(0xffffffffu, idx, src);
            if (uv > umin) {             // umin warp-uniform -> uniform branch
                if (lane == minlane) { lu = uv; lidx = vi; }
                umin = __reduce_min_sync(0xffffffffu, lu);
                minlane = __ffs(__ballot_sync(0xffffffffu, lu == umin)) - 1;
            }
        }
    }

    // softmax over the 32 survivors (== reference masked softmax: masked
    // entries contribute exp(-1e9 - max) == 0 in fp32)
    const float lval = mono2f(lu);
    const float m = warp_max(lval);
    const float e = __expf(lval - m);
    const float w = e / warp_sum(e);

    // AV gather: lane owns output dims (2*lane, 2*lane+1)
    const float* Vb = g_Vp + (size_t)b * NS * ND + h * NDK + lane * 2;
    float2 acc = make_float2(0.f, 0.f);
#pragma unroll
    for (int t = 0; t < 32; t++) {
        const int   vi = __shfl_sync(0xffffffffu, lidx, t);
        const float wt = __shfl_sync(0xffffffffu, w, t);
        const float2 v = *(const float2*)(Vb + (size_t)vi * ND);
        acc.x += wt * v.x;
        acc.y += wt * v.y;
    }

    *(float2*)(out + (size_t)(b * NS + s) * ND + h * NDK + lane * 2) = acc;
}

// ---------------------------------------------------------------------------
extern "C" void kernel_launch(void* const* d_in, const int* in_sizes, int n_in,
                              void* d_out, int out_size)
{
    const float* query = (const float*)d_in[0];
    const float* key   = (const float*)d_in[1];
    const float* value = (const float*)d_in[2];
    const float* Wq    = (const float*)d_in[3];
    const float* bq    = (const float*)d_in[4];
    const float* Wk    = (const float*)d_in[5];
    const float* bk    = (const float*)d_in[6];
    const float* Wv    = (const float*)d_in[7];
    const float* bv    = (const float*)d_in[8];
    float* out = (float*)d_out;

    dim3 pgrid(ND / 128, (NB * NS) / 128, 3);
    proj_kernel<<<pgrid, 256>>>(query, Wq, bq, key, Wk, bk, value, Wv, bv);

    dim3 sgrid(NS / 128, NS / 128, NB * NH);
    score_kernel<<<sgrid, 256>>>();

    select_kernel<<<(NB * NH * NS) / 8, 256>>>(out);
}